// round 1
// baseline (speedup 1.0000x reference)
#include <cuda_runtime.h>
#include <cstdint>

// Problem shape (fixed by reference setup_inputs)
#define B_ 8
#define C_ 128
#define H_ 256
#define W_ 256
#define N_ (H_ * W_)   // 65536 pixels per image
#define S_ 1024        // segments per image

// Scratch for per-(b,seg) pixel counts (allocation-free: __device__ global)
__device__ float g_counts[B_ * S_];

// ---------------------------------------------------------------------------
// Zero the counts scratch (must run every launch; graph replays the whole seq)
// ---------------------------------------------------------------------------
__global__ void zero_counts_kernel() {
    int i = blockIdx.x * blockDim.x + threadIdx.x;
    if (i < B_ * S_) g_counts[i] = 0.0f;
}

// ---------------------------------------------------------------------------
// Per-CTA shared-memory histogram of labels -> global counts
// grid: (N_/8192, B_), block: 256
// ---------------------------------------------------------------------------
__global__ void count_kernel(const int* __restrict__ labels) {
    __shared__ int hist[S_];
    for (int i = threadIdx.x; i < S_; i += blockDim.x) hist[i] = 0;
    __syncthreads();

    const int b = blockIdx.y;
    const int base = b * N_ + blockIdx.x * 8192;
    #pragma unroll 4
    for (int i = threadIdx.x; i < 8192; i += blockDim.x) {
        atomicAdd(&hist[labels[base + i]], 1);
    }
    __syncthreads();

    for (int i = threadIdx.x; i < S_; i += blockDim.x) {
        int v = hist[i];
        if (v) atomicAdd(&g_counts[b * S_ + i], (float)v);
    }
}

// ---------------------------------------------------------------------------
// Scatter: each thread reads one pixel from 4 consecutive channel planes
// (4 coalesced warp loads) and issues ONE red.global.add.v4.f32 into
// out[b, seg, cg*4 .. cg*4+3] (16B-aligned, C contiguous in output).
// grid: (16 pixel-chunks, C_/4 channel-groups, B_), block: 256
// Each thread handles 16 pixels (4096-pixel chunk / 256 threads).
// ---------------------------------------------------------------------------
__global__ void __launch_bounds__(256) scatter_kernel(
    const float* __restrict__ in,
    const int* __restrict__ labels,
    float* __restrict__ out)
{
    const int b     = blockIdx.z;
    const int cg    = blockIdx.y;    // channel group of 4
    const int chunk = blockIdx.x;    // 4096-pixel spatial chunk
    const int t     = threadIdx.x;

    const float* p0  = in + ((size_t)b * C_ + (size_t)cg * 4) * N_;
    const int*   lab = labels + (size_t)b * N_ + chunk * 4096;
    float*       ob  = out + (size_t)b * S_ * C_ + cg * 4;

    #pragma unroll
    for (int i = 0; i < 16; i++) {
        const int off = i * 256 + t;          // 0..4095 within chunk
        const int n   = chunk * 4096 + off;   // pixel index within image
        const int seg = lab[off];

        const float x = p0[n];
        const float y = p0[N_ + n];
        const float z = p0[2 * N_ + n];
        const float w = p0[3 * N_ + n];

        float* addr = ob + (size_t)seg * C_;
        asm volatile(
            "red.global.add.v4.f32 [%0], {%1, %2, %3, %4};"
            :: "l"(addr), "f"(x), "f"(y), "f"(z), "f"(w)
            : "memory");
    }
}

// ---------------------------------------------------------------------------
// Finalize: out[b,s,c] = sum / max(count,1), vectorized float4
// ---------------------------------------------------------------------------
__global__ void finalize_kernel(float* __restrict__ out) {
    const int t = blockIdx.x * blockDim.x + threadIdx.x;   // over B*S*C/4
    if (t >= B_ * S_ * C_ / 4) return;
    const int bs = t / (C_ / 4);
    const float cnt = g_counts[bs];
    const float scale = 1.0f / fmaxf(cnt, 1.0f);
    float4* o = reinterpret_cast<float4*>(out);
    float4 v = o[t];
    v.x *= scale; v.y *= scale; v.z *= scale; v.w *= scale;
    o[t] = v;
}

// ---------------------------------------------------------------------------
// kernel_launch: zero -> count -> scatter -> finalize, all on default stream
// (graph-capturable: only kernel launches + one async memset; no allocs)
// ---------------------------------------------------------------------------
extern "C" void kernel_launch(void* const* d_in, const int* in_sizes, int n_in,
                              void* d_out, int out_size) {
    const float* in     = (const float*)d_in[0];
    const int*   labels = (const int*)d_in[1];
    float*       out    = (float*)d_out;

    // Zero the accumulation target (d_out is poisoned before timing)
    cudaMemsetAsync(d_out, 0, (size_t)out_size * sizeof(float), 0);
    zero_counts_kernel<<<(B_ * S_ + 255) / 256, 256>>>();

    count_kernel<<<dim3(N_ / 8192, B_), 256>>>(labels);

    scatter_kernel<<<dim3(16, C_ / 4, B_), 256>>>(in, labels, out);

    finalize_kernel<<<(B_ * S_ * C_ / 4 + 255) / 256, 256>>>(out);
}

// round 2
// speedup vs baseline: 1.0862x; 1.0862x over previous
#include <cuda_runtime.h>
#include <cstdint>

// Problem shape (fixed by reference setup_inputs)
#define B_ 8
#define C_ 128
#define H_ 256
#define W_ 256
#define N_ (H_ * W_)   // 65536 pixels per image
#define S_ 1024        // segments per image
#define PLANE4 (N_ / 4)  // plane stride in float4 units = 16384

// Scratch for per-(b,seg) pixel counts. Zero at static init; every
// kernel_launch call restores it to zero at the end (zero_counts last),
// so the "counts are zero on entry" invariant holds across graph replays.
__device__ float g_counts[B_ * S_];

// ---------------------------------------------------------------------------
// Zero the output accumulator (d_out is poisoned before timing)
// ---------------------------------------------------------------------------
__global__ void zero_out_kernel(float4* __restrict__ out) {
    const int i = blockIdx.x * blockDim.x + threadIdx.x;   // over B*S*C/4
    out[i] = make_float4(0.f, 0.f, 0.f, 0.f);
}

// ---------------------------------------------------------------------------
// Zero the counts scratch for the NEXT invocation (runs last each call)
// ---------------------------------------------------------------------------
__global__ void zero_counts_kernel() {
    int i = blockIdx.x * blockDim.x + threadIdx.x;
    if (i < B_ * S_) g_counts[i] = 0.0f;
}

// ---------------------------------------------------------------------------
// Scatter + fused count.
// grid: (16 pixel-chunks, C_/4 channel-groups, B_), block: 256.
// Each thread handles 4 groups of 4 consecutive pixels:
//   - 4x LDG.128 (one float4 per channel plane, coalesced)
//   - 1x LDG.128 (int4 labels)
//   - 4x red.global.add.v4.f32 into out[b, seg, cg*4 .. cg*4+3]
// cg==0 blocks additionally build a per-CTA smem histogram of their 4096
// labels and flush it atomically to g_counts (replaces the count kernel).
// ---------------------------------------------------------------------------
__global__ void __launch_bounds__(256) scatter_kernel(
    const float* __restrict__ in,
    const int* __restrict__ labels,
    float* __restrict__ out)
{
    __shared__ int hist[S_];

    const int b     = blockIdx.z;
    const int cg    = blockIdx.y;    // channel group of 4
    const int chunk = blockIdx.x;    // 4096-pixel spatial chunk
    const int t     = threadIdx.x;
    const bool do_count = (cg == 0);   // uniform per block

    if (do_count) {
        for (int i = t; i < S_; i += 256) hist[i] = 0;
        __syncthreads();
    }

    // base of this block's 4-channel plane group, offset to its chunk
    const float4* p0 = reinterpret_cast<const float4*>(
                           in + ((size_t)b * C_ + (size_t)cg * 4) * N_)
                       + chunk * 1024;
    const int4* lab4 = reinterpret_cast<const int4*>(
                           labels + (size_t)b * N_ + chunk * 4096);
    float* ob = out + (size_t)b * S_ * C_ + cg * 4;

    #pragma unroll
    for (int g = 0; g < 4; g++) {
        const int idx = g * 256 + t;          // float4 index within chunk
        const float4 x0 = p0[idx];                 // channel cg*4+0, pixels p..p+3
        const float4 x1 = p0[PLANE4     + idx];    // channel cg*4+1
        const float4 x2 = p0[2 * PLANE4 + idx];    // channel cg*4+2
        const float4 x3 = p0[3 * PLANE4 + idx];    // channel cg*4+3
        const int4 sg = lab4[idx];

        if (do_count) {
            atomicAdd(&hist[sg.x], 1);
            atomicAdd(&hist[sg.y], 1);
            atomicAdd(&hist[sg.z], 1);
            atomicAdd(&hist[sg.w], 1);
        }

        float* a0 = ob + (size_t)sg.x * C_;
        float* a1 = ob + (size_t)sg.y * C_;
        float* a2 = ob + (size_t)sg.z * C_;
        float* a3 = ob + (size_t)sg.w * C_;
        asm volatile("red.global.add.v4.f32 [%0], {%1, %2, %3, %4};"
                     :: "l"(a0), "f"(x0.x), "f"(x1.x), "f"(x2.x), "f"(x3.x) : "memory");
        asm volatile("red.global.add.v4.f32 [%0], {%1, %2, %3, %4};"
                     :: "l"(a1), "f"(x0.y), "f"(x1.y), "f"(x2.y), "f"(x3.y) : "memory");
        asm volatile("red.global.add.v4.f32 [%0], {%1, %2, %3, %4};"
                     :: "l"(a2), "f"(x0.z), "f"(x1.z), "f"(x2.z), "f"(x3.z) : "memory");
        asm volatile("red.global.add.v4.f32 [%0], {%1, %2, %3, %4};"
                     :: "l"(a3), "f"(x0.w), "f"(x1.w), "f"(x2.w), "f"(x3.w) : "memory");
    }

    if (do_count) {
        __syncthreads();
        for (int i = t; i < S_; i += 256) {
            int v = hist[i];
            if (v) atomicAdd(&g_counts[b * S_ + i], (float)v);
        }
    }
}

// ---------------------------------------------------------------------------
// Finalize: out[b,s,c] = sum / max(count,1), vectorized float4
// ---------------------------------------------------------------------------
__global__ void __launch_bounds__(256) finalize_kernel(float* __restrict__ out) {
    const int t = blockIdx.x * blockDim.x + threadIdx.x;   // over B*S*C/4
    const int bs = t / (C_ / 4);
    const float cnt = g_counts[bs];
    const float scale = 1.0f / fmaxf(cnt, 1.0f);
    float4* o = reinterpret_cast<float4*>(out);
    float4 v = o[t];
    v.x *= scale; v.y *= scale; v.z *= scale; v.w *= scale;
    o[t] = v;
}

// ---------------------------------------------------------------------------
// kernel_launch: zero_out -> scatter(+count) -> finalize -> zero_counts
// 4 launches/iteration so ncu (-s 5 -c 1) lands on iteration 2's scatter.
// Graph-capturable: kernel launches only, no allocs.
// ---------------------------------------------------------------------------
extern "C" void kernel_launch(void* const* d_in, const int* in_sizes, int n_in,
                              void* d_out, int out_size) {
    const float* in     = (const float*)d_in[0];
    const int*   labels = (const int*)d_in[1];
    float*       out    = (float*)d_out;

    zero_out_kernel<<<B_ * S_ * C_ / 4 / 256, 256>>>((float4*)d_out);

    scatter_kernel<<<dim3(16, C_ / 4, B_), 256>>>(in, labels, out);

    finalize_kernel<<<B_ * S_ * C_ / 4 / 256, 256>>>(out);

    zero_counts_kernel<<<(B_ * S_ + 255) / 256, 256>>>();
}